// round 12
// baseline (speedup 1.0000x reference)
#include <cuda_runtime.h>
#include <cuda_fp16.h>

#define BG 128
#define NN 128
#define NE 262144
#define NSUM (BG*NN)   // 16384
#define CAP 96

typedef unsigned int u32;

// ---------------- scratch (static device globals; no runtime alloc) --------
__device__ float g_hbn[NSUM*256];    // per node [m][c] fp32, c fast   16 MB
__device__ u32   g_h1h[NSUM*512];    // per node [m][d] fp16 pairs     32 MB
__device__ int   g_cnt [NSUM];
__device__ int   g_adj [NSUM*CAP];

// ---------------- tf32 mma helpers ----------------------------------------
__device__ __forceinline__ u32 f2tf(float f) {
    u32 r; asm("cvt.rna.tf32.f32 %0, %1;" : "=r"(r) : "f"(f)); return r;
}
__device__ __forceinline__ void mma8(float4& c, u32 a0, u32 a1, u32 a2, u32 a3,
                                     u32 b0, u32 b1) {
    asm("mma.sync.aligned.m16n8k8.row.col.f32.tf32.tf32.f32 "
        "{%0,%1,%2,%3},{%4,%5,%6,%7},{%8,%9},{%0,%1,%2,%3};"
        : "+f"(c.x), "+f"(c.y), "+f"(c.z), "+f"(c.w)
        : "r"(a0), "r"(a1), "r"(a2), "r"(a3), "r"(b0), "r"(b1));
}
__device__ __forceinline__ u32 h2pack(float a, float b) {
    __half2 h = __floats2half2_rn(a, b);
    return *(u32*)&h;
}

// ================= Kernel A: poly filter + MLP + BatchNorm + ReLU =========
__global__ __launch_bounds__(512) void kA(
    const float* __restrict__ lap, const float* __restrict__ W0,
    const float* __restrict__ mlpW, const float* __restrict__ mlpb,
    const float* __restrict__ bng,  const float* __restrict__ bnb)
{
    extern __shared__ float sm[];
    float* lap_s = sm;                    // 128*132
    float* w_s   = lap_s + 128*132;       // 2*2064
    float* mw_s  = w_s + 2*2064;          // 128
    float* redS  = mw_s + 128;            // 256
    float* redQ  = redS + 256;            // 256
    float* a_s   = redQ + 256;            // 16
    float* c_s   = a_s + 16;              // 16

    const int b = blockIdx.x, tid = threadIdx.x;
    const float* lb = lap + (size_t)b*NN*NN;
    for (int q = tid; q < NN*NN/4; q += 512) {
        int n = q >> 5, j4 = (q & 31) << 2;
        *(float4*)(lap_s + n*132 + j4) = *(const float4*)(lb + n*NN + j4);
    }
    if (tid < 128) mw_s[tid] = mlpW[tid];

    const int m = tid & 15, g = tid >> 4, n0 = g << 2;

    float hacc[4][16];
    #pragma unroll
    for (int r = 0; r < 4; r++)
        #pragma unroll
        for (int c = 0; c < 16; c++) hacc[r][c] = 0.f;

    float wv[4];
    #pragma unroll
    for (int r = 0; r < 4; r++) {
        wv[r] = W0[(size_t)b*NN*16 + (n0+r)*16 + m];
        w_s[m*129 + n0 + r] = wv[r];
    }
    __syncthreads();
    #pragma unroll
    for (int r = 0; r < 4; r++)
        #pragma unroll
        for (int c = 0; c < 16; c++) hacc[r][c] += wv[r]*mw_s[c];

    int cur = 0;
    for (int k = 1; k < 8; k++) {
        float acc0=0.f, acc1=0.f, acc2=0.f, acc3=0.f;
        const float* wr = w_s + cur*2064 + m*129;
        const float* l0 = lap_s + (n0+0)*132;
        const float* l1 = lap_s + (n0+1)*132;
        const float* l2 = lap_s + (n0+2)*132;
        const float* l3 = lap_s + (n0+3)*132;
        #pragma unroll 8
        for (int j = 0; j < NN; j += 4) {
            float w0=wr[j], w1=wr[j+1], w2=wr[j+2], w3=wr[j+3];
            float4 a  = *(const float4*)(l0+j);
            float4 b4 = *(const float4*)(l1+j);
            float4 c4 = *(const float4*)(l2+j);
            float4 d4 = *(const float4*)(l3+j);
            acc0 += a.x *w0 + a.y *w1 + a.z *w2 + a.w *w3;
            acc1 += b4.x*w0 + b4.y*w1 + b4.z*w2 + b4.w*w3;
            acc2 += c4.x*w0 + c4.y*w1 + c4.z*w2 + c4.w*w3;
            acc3 += d4.x*w0 + d4.y*w1 + d4.z*w2 + d4.w*w3;
        }
        float* wn = w_s + (cur^1)*2064 + m*129;
        wn[n0]=acc0; wn[n0+1]=acc1; wn[n0+2]=acc2; wn[n0+3]=acc3;
        const float* mw = mw_s + k*16;
        float av[4] = {acc0, acc1, acc2, acc3};
        #pragma unroll
        for (int r = 0; r < 4; r++)
            #pragma unroll
            for (int c = 0; c < 16; c++) hacc[r][c] += av[r]*mw[c];
        __syncthreads();
        cur ^= 1;
    }
    #pragma unroll
    for (int c = 0; c < 16; c++) {
        float bb = mlpb[c];
        #pragma unroll
        for (int r = 0; r < 4; r++) hacc[r][c] += bb;
    }
    float s[16], q[16];
    #pragma unroll
    for (int c = 0; c < 16; c++) {
        s[c] = hacc[0][c]+hacc[1][c]+hacc[2][c]+hacc[3][c];
        q[c] = hacc[0][c]*hacc[0][c]+hacc[1][c]*hacc[1][c]
             + hacc[2][c]*hacc[2][c]+hacc[3][c]*hacc[3][c];
    }
    #pragma unroll
    for (int o = 16; o > 0; o >>= 1) {
        #pragma unroll
        for (int c = 0; c < 16; c++) {
            s[c] += __shfl_xor_sync(0xffffffffu, s[c], o);
            q[c] += __shfl_xor_sync(0xffffffffu, q[c], o);
        }
    }
    const int warp = tid >> 5, lane = tid & 31;
    if (lane == 0) {
        #pragma unroll
        for (int c = 0; c < 16; c++) { redS[warp*16+c]=s[c]; redQ[warp*16+c]=q[c]; }
    }
    __syncthreads();
    if (tid < 16) {
        float S=0.f, Q=0.f;
        #pragma unroll
        for (int w = 0; w < 16; w++) { S += redS[w*16+tid]; Q += redQ[w*16+tid]; }
        float mean = S * (1.0f/2048.0f);
        float var  = Q * (1.0f/2048.0f) - mean*mean;
        float rstd = rsqrtf(var + 1e-5f);
        float gch  = bng[tid];
        a_s[tid] = rstd * gch;
        c_s[tid] = bnb[tid] - mean * rstd * gch;
    }
    __syncthreads();
    #pragma unroll
    for (int r = 0; r < 4; r++) {
        float tmp[16];
        #pragma unroll
        for (int c = 0; c < 16; c++)
            tmp[c] = fmaxf(hacc[r][c]*a_s[c] + c_s[c], 0.f);
        float* dst = g_hbn + ((size_t)(b*NN + n0 + r))*256 + m*16;
        *(float4*)(dst+ 0) = make_float4(tmp[0], tmp[1], tmp[2], tmp[3]);
        *(float4*)(dst+ 4) = make_float4(tmp[4], tmp[5], tmp[6], tmp[7]);
        *(float4*)(dst+ 8) = make_float4(tmp[8], tmp[9], tmp[10],tmp[11]);
        *(float4*)(dst+12) = make_float4(tmp[12],tmp[13],tmp[14],tmp[15]);
    }
}

// ================= padded-bucket adjacency ================================
__global__ void kZero() {
    int i = blockIdx.x*blockDim.x + threadIdx.x;
    if (i < NSUM) g_cnt[i] = 0;
}
__global__ void kFill(const int* __restrict__ ei) {
    int i = blockIdx.x*blockDim.x + threadIdx.x;
    if (i < NE) {
        int src = ei[i], dst = ei[NE + i];
        int p = atomicAdd(&g_cnt[dst], 1);
        if (p < CAP) g_adj[dst*CAP + p] = src;
    }
}

// ================= Kernel C: GIN layer 1 (tf32 mma, frag-layout weights) ===
// 8 warps/block, 2 nodes/warp. z shares the t buffer (cols 0-15, overwritten
// after GEMM1). Weights pre-arranged per-lane: Wf[k][lane][16], stride 20.
__global__ __launch_bounds__(256, 2) void kGin1(
    const float* __restrict__ eps1p,
    const float* __restrict__ W1a, const float* __restrict__ b1a,
    const float* __restrict__ W1b, const float* __restrict__ b1b)
{
    extern __shared__ u32 sh1[];
    u32*   WaF = sh1;                  // 2*640 = 1280
    u32*   WbF = WaF + 1280;           // 8*640 = 5120
    float* bia = (float*)(WbF + 5120); // 64
    float* bib = bia + 64;             // 64
    u32*   tS  = (u32*)(bib + 64);     // 16 * 1088 = 17408

    const int tid = threadIdx.x;
    for (int i = tid; i < 1024; i += 256) {
        int k = i >> 9, l2 = (i >> 4) & 31, j = i & 15;
        int c = k*8 + (l2 & 3) + ((j >= 8) ? 4 : 0);
        int d = (j & 7)*8 + (l2 >> 2);
        WaF[k*640 + l2*20 + j] = f2tf(W1a[c*64 + d]);
    }
    for (int i = tid; i < 4096; i += 256) {
        int k = i >> 9, l2 = (i >> 4) & 31, j = i & 15;
        int c = k*8 + (l2 & 3) + ((j >= 8) ? 4 : 0);
        int d = (j & 7)*8 + (l2 >> 2);
        WbF[k*640 + l2*20 + j] = f2tf(W1b[c*64 + d]);
    }
    if (tid < 64) { bia[tid] = b1a[tid]; bib[tid] = b1b[tid]; }
    __syncthreads();

    const int lane = tid & 31, w = tid >> 5;
    const int q = lane & 3, r = lane >> 2;
    const int vb = blockIdx.x*16 + w*2;
    const float eps = 1.0f + eps1p[0];

    // ---- aggregation (fp32 hbn) -> z into t buffer cols 0-15 ----
    #pragma unroll
    for (int nd = 0; nd < 2; nd++) {
        const int v = vb + nd;
        u32* tb = tS + (w*2 + nd)*1088;
        float4 A0 = make_float4(0.f,0.f,0.f,0.f), A1 = A0;
        const int cnt = min(g_cnt[v], CAP);
        const int* adj = g_adj + v*CAP;
        #pragma unroll 2
        for (int e = 0; e < cnt; e++) {
            const float* src = g_hbn + (size_t)adj[e]*256 + lane*4;
            float4 x = *(const float4*)(src);
            float4 y = *(const float4*)(src + 128);
            A0.x+=x.x; A0.y+=x.y; A0.z+=x.z; A0.w+=x.w;
            A1.x+=y.x; A1.y+=y.y; A1.z+=y.z; A1.w+=y.w;
        }
        const float* own = g_hbn + (size_t)v*256 + lane*4;
        float4 o0 = *(const float4*)(own);
        float4 o1 = *(const float4*)(own + 128);
        uint4 z0, z1;
        z0.x=f2tf(fmaf(eps,o0.x,A0.x)); z0.y=f2tf(fmaf(eps,o0.y,A0.y));
        z0.z=f2tf(fmaf(eps,o0.z,A0.z)); z0.w=f2tf(fmaf(eps,o0.w,A0.w));
        z1.x=f2tf(fmaf(eps,o1.x,A1.x)); z1.y=f2tf(fmaf(eps,o1.y,A1.y));
        z1.z=f2tf(fmaf(eps,o1.z,A1.z)); z1.w=f2tf(fmaf(eps,o1.w,A1.w));
        *(uint4*)(tb + r*68 + q*4)     = z0;
        *(uint4*)(tb + (8+r)*68 + q*4) = z1;
    }
    __syncwarp();

    float4 C[2][8];
    // ---- GEMM1: z[16,16] @ W1a ----
    #pragma unroll
    for (int nd = 0; nd < 2; nd++)
        #pragma unroll
        for (int n = 0; n < 8; n++) {
            float2 bv = *(const float2*)(bia + n*8 + 2*q);
            C[nd][n] = make_float4(bv.x, bv.y, bv.x, bv.y);
        }
    #pragma unroll
    for (int k = 0; k < 2; k++) {
        const u32* wp = WaF + k*640 + lane*20;
        uint4 f0 = *(const uint4*)(wp);
        uint4 f1 = *(const uint4*)(wp + 4);
        uint4 f2 = *(const uint4*)(wp + 8);
        uint4 f3 = *(const uint4*)(wp + 12);
        u32 b0[8] = {f0.x,f0.y,f0.z,f0.w, f1.x,f1.y,f1.z,f1.w};
        u32 b1[8] = {f2.x,f2.y,f2.z,f2.w, f3.x,f3.y,f3.z,f3.w};
        #pragma unroll
        for (int nd = 0; nd < 2; nd++) {
            const u32* tb = tS + (w*2 + nd)*1088;
            u32 a0 = tb[r*68 + k*8 + q];
            u32 a1 = tb[(8+r)*68 + k*8 + q];
            u32 a2 = tb[r*68 + k*8 + q + 4];
            u32 a3 = tb[(8+r)*68 + k*8 + q + 4];
            #pragma unroll
            for (int n = 0; n < 8; n++) mma8(C[nd][n], a0, a1, a2, a3, b0[n], b1[n]);
        }
    }
    __syncwarp();
    // relu + cvt -> t (overwrites z region)
    #pragma unroll
    for (int nd = 0; nd < 2; nd++) {
        u32* tb = tS + (w*2 + nd)*1088;
        #pragma unroll
        for (int n = 0; n < 8; n++) {
            float4 c = C[nd][n];
            *(uint2*)(tb + r*68 + n*8 + 2*q)     = make_uint2(f2tf(fmaxf(c.x,0.f)), f2tf(fmaxf(c.y,0.f)));
            *(uint2*)(tb + (8+r)*68 + n*8 + 2*q) = make_uint2(f2tf(fmaxf(c.z,0.f)), f2tf(fmaxf(c.w,0.f)));
        }
    }
    __syncwarp();

    // ---- GEMM2: t[16,64] @ W1b -> h1 (fp16) ----
    #pragma unroll
    for (int nd = 0; nd < 2; nd++)
        #pragma unroll
        for (int n = 0; n < 8; n++) {
            float2 bv = *(const float2*)(bib + n*8 + 2*q);
            C[nd][n] = make_float4(bv.x, bv.y, bv.x, bv.y);
        }
    #pragma unroll
    for (int k = 0; k < 8; k++) {
        const u32* wp = WbF + k*640 + lane*20;
        uint4 f0 = *(const uint4*)(wp);
        uint4 f1 = *(const uint4*)(wp + 4);
        uint4 f2 = *(const uint4*)(wp + 8);
        uint4 f3 = *(const uint4*)(wp + 12);
        u32 b0[8] = {f0.x,f0.y,f0.z,f0.w, f1.x,f1.y,f1.z,f1.w};
        u32 b1[8] = {f2.x,f2.y,f2.z,f2.w, f3.x,f3.y,f3.z,f3.w};
        #pragma unroll
        for (int nd = 0; nd < 2; nd++) {
            const u32* tb = tS + (w*2 + nd)*1088;
            u32 a0 = tb[r*68 + k*8 + q];
            u32 a1 = tb[(8+r)*68 + k*8 + q];
            u32 a2 = tb[r*68 + k*8 + q + 4];
            u32 a3 = tb[(8+r)*68 + k*8 + q + 4];
            #pragma unroll
            for (int n = 0; n < 8; n++) mma8(C[nd][n], a0, a1, a2, a3, b0[n], b1[n]);
        }
    }
    #pragma unroll
    for (int nd = 0; nd < 2; nd++) {
        u32* o = g_h1h + (size_t)(vb + nd)*512;
        #pragma unroll
        for (int n = 0; n < 8; n++) {
            float4 c = C[nd][n];
            o[r*32 + n*4 + q]     = h2pack(fmaxf(c.x,0.f), fmaxf(c.y,0.f));
            o[(8+r)*32 + n*4 + q] = h2pack(fmaxf(c.z,0.f), fmaxf(c.w,0.f));
        }
    }
}

// ================= Kernel D: GIN layer 2 + sample-sum (fp16 gather) ========
__global__ __launch_bounds__(256, 2) void kGin2(
    const float* __restrict__ eps2p,
    const float* __restrict__ W2a, const float* __restrict__ b2a,
    const float* __restrict__ W2b, const float* __restrict__ b2b,
    float* __restrict__ out)
{
    extern __shared__ u32 sh2[];
    u32*   WaF = sh2;                  // 8*640 = 5120
    u32*   WbF = WaF + 5120;           // 5120
    float* bia = (float*)(WbF + 5120); // 64
    float* bib = bia + 64;             // 64
    u32*   zS  = (u32*)(bib + 64);     // 16 * 1088 = 17408 (z then t)

    const int tid = threadIdx.x;
    for (int i = tid; i < 4096; i += 256) {
        int k = i >> 9, l2 = (i >> 4) & 31, j = i & 15;
        int c = k*8 + (l2 & 3) + ((j >= 8) ? 4 : 0);
        int d = (j & 7)*8 + (l2 >> 2);
        WaF[k*640 + l2*20 + j] = f2tf(W2a[c*64 + d]);
        WbF[k*640 + l2*20 + j] = f2tf(W2b[c*64 + d]);
    }
    if (tid < 64) { bia[tid] = b2a[tid]; bib[tid] = b2b[tid]; }
    __syncthreads();

    const int lane = tid & 31, w = tid >> 5;
    const int q = lane & 3, r = lane >> 2;
    const int vb = blockIdx.x*16 + w*2;
    const float eps = 1.0f + eps2p[0];

    // ---- aggregation (fp16 loads, fp32 accum) -> z smem (tf32, stride 68) --
    #pragma unroll
    for (int nd = 0; nd < 2; nd++) {
        const int v = vb + nd;
        u32* zb = zS + (w*2 + nd)*1088;
        float2 acc[16];
        #pragma unroll
        for (int i = 0; i < 16; i++) acc[i] = make_float2(0.f, 0.f);
        const int cnt = min(g_cnt[v], CAP);
        const int* adj = g_adj + v*CAP;
        #pragma unroll 2
        for (int e = 0; e < cnt; e++) {
            const uint4* p = (const uint4*)(g_h1h + (size_t)adj[e]*512 + lane*16);
            #pragma unroll
            for (int i = 0; i < 4; i++) {
                uint4 x = p[i];
                u32 xs[4] = {x.x, x.y, x.z, x.w};
                #pragma unroll
                for (int j2 = 0; j2 < 4; j2++) {
                    float2 f = __half22float2(*(const __half2*)&xs[j2]);
                    acc[i*4+j2].x += f.x; acc[i*4+j2].y += f.y;
                }
            }
        }
        u32 zt[32];
        const uint4* ownp = (const uint4*)(g_h1h + (size_t)v*512 + lane*16);
        #pragma unroll
        for (int i = 0; i < 4; i++) {
            uint4 o = ownp[i];
            u32 os[4] = {o.x, o.y, o.z, o.w};
            #pragma unroll
            for (int j2 = 0; j2 < 4; j2++) {
                float2 f = __half22float2(*(const __half2*)&os[j2]);
                float2 a = acc[i*4+j2];
                zt[(i*4+j2)*2]   = f2tf(fmaf(eps, f.x, a.x));
                zt[(i*4+j2)*2+1] = f2tf(fmaf(eps, f.y, a.y));
            }
        }
        u32* zw = zb + (lane >> 1)*68 + (lane & 1)*32;
        #pragma unroll
        for (int i = 0; i < 8; i++)
            *(uint4*)(zw + i*4) = make_uint4(zt[i*4], zt[i*4+1], zt[i*4+2], zt[i*4+3]);
    }
    __syncwarp();

    float4 C[2][8];
    // ---- GEMM1: z @ W2a + b2a, relu ----
    #pragma unroll
    for (int nd = 0; nd < 2; nd++)
        #pragma unroll
        for (int n = 0; n < 8; n++) {
            float2 bv = *(const float2*)(bia + n*8 + 2*q);
            C[nd][n] = make_float4(bv.x, bv.y, bv.x, bv.y);
        }
    #pragma unroll
    for (int k = 0; k < 8; k++) {
        const u32* wp = WaF + k*640 + lane*20;
        uint4 f0 = *(const uint4*)(wp);
        uint4 f1 = *(const uint4*)(wp + 4);
        uint4 f2 = *(const uint4*)(wp + 8);
        uint4 f3 = *(const uint4*)(wp + 12);
        u32 b0[8] = {f0.x,f0.y,f0.z,f0.w, f1.x,f1.y,f1.z,f1.w};
        u32 b1[8] = {f2.x,f2.y,f2.z,f2.w, f3.x,f3.y,f3.z,f3.w};
        #pragma unroll
        for (int nd = 0; nd < 2; nd++) {
            const u32* zb = zS + (w*2 + nd)*1088;
            u32 a0 = zb[r*68 + k*8 + q];
            u32 a1 = zb[(8+r)*68 + k*8 + q];
            u32 a2 = zb[r*68 + k*8 + q + 4];
            u32 a3 = zb[(8+r)*68 + k*8 + q + 4];
            #pragma unroll
            for (int n = 0; n < 8; n++) mma8(C[nd][n], a0, a1, a2, a3, b0[n], b1[n]);
        }
    }
    __syncwarp();
    // relu + cvt -> t (overwrite z buffer)
    #pragma unroll
    for (int nd = 0; nd < 2; nd++) {
        u32* tb = zS + (w*2 + nd)*1088;
        #pragma unroll
        for (int n = 0; n < 8; n++) {
            float4 c = C[nd][n];
            *(uint2*)(tb + r*68 + n*8 + 2*q)     = make_uint2(f2tf(fmaxf(c.x,0.f)), f2tf(fmaxf(c.y,0.f)));
            *(uint2*)(tb + (8+r)*68 + n*8 + 2*q) = make_uint2(f2tf(fmaxf(c.z,0.f)), f2tf(fmaxf(c.w,0.f)));
        }
    }
    __syncwarp();

    // ---- GEMM2: t @ W2b + b2b, relu, sum over m ----
    #pragma unroll
    for (int nd = 0; nd < 2; nd++)
        #pragma unroll
        for (int n = 0; n < 8; n++) {
            float2 bv = *(const float2*)(bib + n*8 + 2*q);
            C[nd][n] = make_float4(bv.x, bv.y, bv.x, bv.y);
        }
    #pragma unroll
    for (int k = 0; k < 8; k++) {
        const u32* wp = WbF + k*640 + lane*20;
        uint4 f0 = *(const uint4*)(wp);
        uint4 f1 = *(const uint4*)(wp + 4);
        uint4 f2 = *(const uint4*)(wp + 8);
        uint4 f3 = *(const uint4*)(wp + 12);
        u32 b0[8] = {f0.x,f0.y,f0.z,f0.w, f1.x,f1.y,f1.z,f1.w};
        u32 b1[8] = {f2.x,f2.y,f2.z,f2.w, f3.x,f3.y,f3.z,f3.w};
        #pragma unroll
        for (int nd = 0; nd < 2; nd++) {
            const u32* tb = zS + (w*2 + nd)*1088;
            u32 a0 = tb[r*68 + k*8 + q];
            u32 a1 = tb[(8+r)*68 + k*8 + q];
            u32 a2 = tb[r*68 + k*8 + q + 4];
            u32 a3 = tb[(8+r)*68 + k*8 + q + 4];
            #pragma unroll
            for (int n = 0; n < 8; n++) mma8(C[nd][n], a0, a1, a2, a3, b0[n], b1[n]);
        }
    }
    #pragma unroll
    for (int nd = 0; nd < 2; nd++) {
        float s0[8], s1[8];
        #pragma unroll
        for (int n = 0; n < 8; n++) {
            float4 c = C[nd][n];
            s0[n] = fmaxf(c.x,0.f) + fmaxf(c.z,0.f);
            s1[n] = fmaxf(c.y,0.f) + fmaxf(c.w,0.f);
        }
        #pragma unroll
        for (int o = 4; o < 32; o <<= 1)
            #pragma unroll
            for (int n = 0; n < 8; n++) {
                s0[n] += __shfl_xor_sync(0xffffffffu, s0[n], o);
                s1[n] += __shfl_xor_sync(0xffffffffu, s1[n], o);
            }
        if (lane < 4) {
            float* op = out + (size_t)(vb + nd)*64;
            #pragma unroll
            for (int n = 0; n < 8; n++)
                *(float2*)(op + n*8 + 2*lane) = make_float2(s0[n], s1[n]);
        }
    }
}

// ================= launch ==================================================
extern "C" void kernel_launch(void* const* d_in, const int* in_sizes, int n_in,
                              void* d_out, int out_size)
{
    const float* lap  = (const float*)d_in[0];
    const float* W0   = (const float*)d_in[1];
    const float* mlpW = (const float*)d_in[2];
    const float* mlpb = (const float*)d_in[3];
    const float* bng  = (const float*)d_in[4];
    const float* bnb  = (const float*)d_in[5];
    const float* eps1 = (const float*)d_in[6];
    const float* W1a  = (const float*)d_in[7];
    const float* b1a  = (const float*)d_in[8];
    const float* W1b  = (const float*)d_in[9];
    const float* b1b  = (const float*)d_in[10];
    const float* eps2 = (const float*)d_in[11];
    const float* W2a  = (const float*)d_in[12];
    const float* b2a  = (const float*)d_in[13];
    const float* W2b  = (const float*)d_in[14];
    const float* b2b  = (const float*)d_in[15];
    const int*   ei   = (const int*)d_in[16];
    float* out = (float*)d_out;

    const int SMEM_A  = 21696 * 4;                               // 86784 B
    const int SMEM_G1 = (1280 + 5120 + 128 + 17408) * 4;         // 95744 B
    const int SMEM_G2 = (5120 + 5120 + 128 + 17408) * 4;         // 111104 B
    cudaFuncSetAttribute(kA,    cudaFuncAttributeMaxDynamicSharedMemorySize, SMEM_A);
    cudaFuncSetAttribute(kGin1, cudaFuncAttributeMaxDynamicSharedMemorySize, SMEM_G1);
    cudaFuncSetAttribute(kGin2, cudaFuncAttributeMaxDynamicSharedMemorySize, SMEM_G2);

    kZero<<<NSUM/256, 256>>>();
    kFill<<<NE/256, 256>>>(ei);
    kA   <<<BG, 512, SMEM_A>>>(lap, W0, mlpW, mlpb, bng, bnb);
    kGin1<<<NSUM/16, 256, SMEM_G1>>>(eps1, W1a, b1a, W1b, b1b);
    kGin2<<<NSUM/16, 256, SMEM_G2>>>(eps2, W2a, b2a, W2b, b2b, out);
}

// round 13
// speedup vs baseline: 1.3091x; 1.3091x over previous
#include <cuda_runtime.h>

#define BG 128
#define NN 128
#define NE 262144
#define NSUM (BG*NN)   // 16384
#define CAP 96

typedef unsigned int u32;

// ---------------- scratch (static device globals; no runtime alloc) --------
__device__ float g_hbn[NSUM*256];    // per node [m][c] fp32, c fast   16 MB
__device__ float g_h1 [NSUM*1024];   // per node [m][d] fp32, d fast   64 MB
__device__ int   g_cnt [NSUM];
__device__ int   g_adj [NSUM*CAP];
// frag-ordered tf32 weights (compact stride 16: slot = k*512 + lane*16 + j)
__device__ u32   g_wf1a[1024];
__device__ u32   g_wf1b[4096];
__device__ u32   g_wf2a[4096];
__device__ u32   g_wf2b[4096];

// ---------------- tf32 mma helpers ----------------------------------------
__device__ __forceinline__ u32 f2tf(float f) {
    u32 r; asm("cvt.rna.tf32.f32 %0, %1;" : "=r"(r) : "f"(f)); return r;
}
__device__ __forceinline__ void mma8(float4& c, u32 a0, u32 a1, u32 a2, u32 a3,
                                     u32 b0, u32 b1) {
    asm("mma.sync.aligned.m16n8k8.row.col.f32.tf32.tf32.f32 "
        "{%0,%1,%2,%3},{%4,%5,%6,%7},{%8,%9},{%0,%1,%2,%3};"
        : "+f"(c.x), "+f"(c.y), "+f"(c.z), "+f"(c.w)
        : "r"(a0), "r"(a1), "r"(a2), "r"(a3), "r"(b0), "r"(b1));
}

// ================= Kernel A: poly filter + MLP + BatchNorm + ReLU =========
__global__ __launch_bounds__(512) void kA(
    const float* __restrict__ lap, const float* __restrict__ W0,
    const float* __restrict__ mlpW, const float* __restrict__ mlpb,
    const float* __restrict__ bng,  const float* __restrict__ bnb)
{
    extern __shared__ float sm[];
    float* lap_s = sm;                    // 128*132
    float* w_s   = lap_s + 128*132;       // 2*2064
    float* mw_s  = w_s + 2*2064;          // 128
    float* redS  = mw_s + 128;            // 256
    float* redQ  = redS + 256;            // 256
    float* a_s   = redQ + 256;            // 16
    float* c_s   = a_s + 16;              // 16

    const int b = blockIdx.x, tid = threadIdx.x;
    const float* lb = lap + (size_t)b*NN*NN;
    for (int q = tid; q < NN*NN/4; q += 512) {
        int n = q >> 5, j4 = (q & 31) << 2;
        *(float4*)(lap_s + n*132 + j4) = *(const float4*)(lb + n*NN + j4);
    }
    if (tid < 128) mw_s[tid] = mlpW[tid];

    const int m = tid & 15, g = tid >> 4, n0 = g << 2;

    float hacc[4][16];
    #pragma unroll
    for (int r = 0; r < 4; r++)
        #pragma unroll
        for (int c = 0; c < 16; c++) hacc[r][c] = 0.f;

    float wv[4];
    #pragma unroll
    for (int r = 0; r < 4; r++) {
        wv[r] = W0[(size_t)b*NN*16 + (n0+r)*16 + m];
        w_s[m*129 + n0 + r] = wv[r];
    }
    __syncthreads();
    #pragma unroll
    for (int r = 0; r < 4; r++)
        #pragma unroll
        for (int c = 0; c < 16; c++) hacc[r][c] += wv[r]*mw_s[c];

    int cur = 0;
    for (int k = 1; k < 8; k++) {
        float acc0=0.f, acc1=0.f, acc2=0.f, acc3=0.f;
        const float* wr = w_s + cur*2064 + m*129;
        const float* l0 = lap_s + (n0+0)*132;
        const float* l1 = lap_s + (n0+1)*132;
        const float* l2 = lap_s + (n0+2)*132;
        const float* l3 = lap_s + (n0+3)*132;
        #pragma unroll 8
        for (int j = 0; j < NN; j += 4) {
            float w0=wr[j], w1=wr[j+1], w2=wr[j+2], w3=wr[j+3];
            float4 a  = *(const float4*)(l0+j);
            float4 b4 = *(const float4*)(l1+j);
            float4 c4 = *(const float4*)(l2+j);
            float4 d4 = *(const float4*)(l3+j);
            acc0 += a.x *w0 + a.y *w1 + a.z *w2 + a.w *w3;
            acc1 += b4.x*w0 + b4.y*w1 + b4.z*w2 + b4.w*w3;
            acc2 += c4.x*w0 + c4.y*w1 + c4.z*w2 + c4.w*w3;
            acc3 += d4.x*w0 + d4.y*w1 + d4.z*w2 + d4.w*w3;
        }
        float* wn = w_s + (cur^1)*2064 + m*129;
        wn[n0]=acc0; wn[n0+1]=acc1; wn[n0+2]=acc2; wn[n0+3]=acc3;
        const float* mw = mw_s + k*16;
        float av[4] = {acc0, acc1, acc2, acc3};
        #pragma unroll
        for (int r = 0; r < 4; r++)
            #pragma unroll
            for (int c = 0; c < 16; c++) hacc[r][c] += av[r]*mw[c];
        __syncthreads();
        cur ^= 1;
    }
    #pragma unroll
    for (int c = 0; c < 16; c++) {
        float bb = mlpb[c];
        #pragma unroll
        for (int r = 0; r < 4; r++) hacc[r][c] += bb;
    }
    float s[16], q[16];
    #pragma unroll
    for (int c = 0; c < 16; c++) {
        s[c] = hacc[0][c]+hacc[1][c]+hacc[2][c]+hacc[3][c];
        q[c] = hacc[0][c]*hacc[0][c]+hacc[1][c]*hacc[1][c]
             + hacc[2][c]*hacc[2][c]+hacc[3][c]*hacc[3][c];
    }
    #pragma unroll
    for (int o = 16; o > 0; o >>= 1) {
        #pragma unroll
        for (int c = 0; c < 16; c++) {
            s[c] += __shfl_xor_sync(0xffffffffu, s[c], o);
            q[c] += __shfl_xor_sync(0xffffffffu, q[c], o);
        }
    }
    const int warp = tid >> 5, lane = tid & 31;
    if (lane == 0) {
        #pragma unroll
        for (int c = 0; c < 16; c++) { redS[warp*16+c]=s[c]; redQ[warp*16+c]=q[c]; }
    }
    __syncthreads();
    if (tid < 16) {
        float S=0.f, Q=0.f;
        #pragma unroll
        for (int w = 0; w < 16; w++) { S += redS[w*16+tid]; Q += redQ[w*16+tid]; }
        float mean = S * (1.0f/2048.0f);
        float var  = Q * (1.0f/2048.0f) - mean*mean;
        float rstd = rsqrtf(var + 1e-5f);
        float gch  = bng[tid];
        a_s[tid] = rstd * gch;
        c_s[tid] = bnb[tid] - mean * rstd * gch;
    }
    __syncthreads();
    #pragma unroll
    for (int r = 0; r < 4; r++) {
        float tmp[16];
        #pragma unroll
        for (int c = 0; c < 16; c++)
            tmp[c] = fmaxf(hacc[r][c]*a_s[c] + c_s[c], 0.f);
        float* dst = g_hbn + ((size_t)(b*NN + n0 + r))*256 + m*16;
        *(float4*)(dst+ 0) = make_float4(tmp[0], tmp[1], tmp[2], tmp[3]);
        *(float4*)(dst+ 4) = make_float4(tmp[4], tmp[5], tmp[6], tmp[7]);
        *(float4*)(dst+ 8) = make_float4(tmp[8], tmp[9], tmp[10],tmp[11]);
        *(float4*)(dst+12) = make_float4(tmp[12],tmp[13],tmp[14],tmp[15]);
    }
}

// ================= adjacency + weight-frag prep ============================
__global__ void kZero() {
    int i = blockIdx.x*blockDim.x + threadIdx.x;
    if (i < NSUM) g_cnt[i] = 0;
}
__global__ void kFill(const int* __restrict__ ei) {
    int i = blockIdx.x*blockDim.x + threadIdx.x;
    if (i < NE) {
        int src = ei[i], dst = ei[NE + i];
        int p = atomicAdd(&g_cnt[dst], 1);
        if (p < CAP) g_adj[dst*CAP + p] = src;
    }
}
// frag slot (k, lane, j): j<8 -> b0[j]: c=k*8+(lane&3), d=j*8+(lane>>2)
//                         j>=8 -> b1[j-8]: c=k*8+(lane&3)+4
__global__ void kFrag(const float* __restrict__ W1a, const float* __restrict__ W1b,
                      const float* __restrict__ W2a, const float* __restrict__ W2b)
{
    int t = blockIdx.x*blockDim.x + threadIdx.x;   // 4096 threads
    int k = t >> 9, l2 = (t >> 4) & 31, j = t & 15;
    int c = k*8 + (l2 & 3) + ((j >= 8) ? 4 : 0);
    int d = (j & 7)*8 + (l2 >> 2);
    int slot = k*512 + l2*16 + j;
    if (t < 1024) g_wf1a[slot] = f2tf(W1a[c*64 + d]);
    g_wf1b[slot] = f2tf(W1b[c*64 + d]);
    g_wf2a[slot] = f2tf(W2a[c*64 + d]);
    g_wf2b[slot] = f2tf(W2b[c*64 + d]);
}

// ================= Kernel C: GIN layer 1 (1 node/warp, LDG weights) ========
__global__ __launch_bounds__(256, 3) void kGin1(
    const float* __restrict__ eps1p,
    const float* __restrict__ b1a, const float* __restrict__ b1b)
{
    extern __shared__ u32 sh1[];
    float* bia = (float*)sh1;          // 64
    float* bib = bia + 64;             // 64
    u32*   tS  = (u32*)(bib + 64);     // 8 * 1088

    const int tid = threadIdx.x;
    if (tid < 64) { bia[tid] = b1a[tid]; bib[tid] = b1b[tid]; }
    __syncthreads();

    const int lane = tid & 31, w = tid >> 5;
    const int q = lane & 3, r = lane >> 2;
    const int v = blockIdx.x*8 + w;
    u32* tb = tS + w*1088;
    const float eps = 1.0f + eps1p[0];

    // ---- aggregation (fp32) -> z into t buffer cols 0-15 ----
    {
        float4 A0 = make_float4(0.f,0.f,0.f,0.f), A1 = A0;
        const int cnt = min(g_cnt[v], CAP);
        const int* adj = g_adj + v*CAP;
        #pragma unroll 2
        for (int e = 0; e < cnt; e++) {
            const float* src = g_hbn + (size_t)adj[e]*256 + lane*4;
            float4 x = *(const float4*)(src);
            float4 y = *(const float4*)(src + 128);
            A0.x+=x.x; A0.y+=x.y; A0.z+=x.z; A0.w+=x.w;
            A1.x+=y.x; A1.y+=y.y; A1.z+=y.z; A1.w+=y.w;
        }
        const float* own = g_hbn + (size_t)v*256 + lane*4;
        float4 o0 = *(const float4*)(own);
        float4 o1 = *(const float4*)(own + 128);
        uint4 z0, z1;
        z0.x=f2tf(fmaf(eps,o0.x,A0.x)); z0.y=f2tf(fmaf(eps,o0.y,A0.y));
        z0.z=f2tf(fmaf(eps,o0.z,A0.z)); z0.w=f2tf(fmaf(eps,o0.w,A0.w));
        z1.x=f2tf(fmaf(eps,o1.x,A1.x)); z1.y=f2tf(fmaf(eps,o1.y,A1.y));
        z1.z=f2tf(fmaf(eps,o1.z,A1.z)); z1.w=f2tf(fmaf(eps,o1.w,A1.w));
        *(uint4*)(tb + r*68 + q*4)     = z0;
        *(uint4*)(tb + (8+r)*68 + q*4) = z1;
    }
    __syncwarp();

    float4 C[8];
    // ---- GEMM1: z[16,16] @ W1a ----
    #pragma unroll
    for (int n = 0; n < 8; n++) {
        float2 bv = *(const float2*)(bia + n*8 + 2*q);
        C[n] = make_float4(bv.x, bv.y, bv.x, bv.y);
    }
    #pragma unroll
    for (int k = 0; k < 2; k++) {
        const uint4* wp = (const uint4*)(g_wf1a + k*512 + lane*16);
        uint4 f0 = __ldg(wp), f1 = __ldg(wp+1), f2 = __ldg(wp+2), f3 = __ldg(wp+3);
        u32 b0[8] = {f0.x,f0.y,f0.z,f0.w, f1.x,f1.y,f1.z,f1.w};
        u32 b1[8] = {f2.x,f2.y,f2.z,f2.w, f3.x,f3.y,f3.z,f3.w};
        u32 a0 = tb[r*68 + k*8 + q];
        u32 a1 = tb[(8+r)*68 + k*8 + q];
        u32 a2 = tb[r*68 + k*8 + q + 4];
        u32 a3 = tb[(8+r)*68 + k*8 + q + 4];
        #pragma unroll
        for (int n = 0; n < 8; n++) mma8(C[n], a0, a1, a2, a3, b0[n], b1[n]);
    }
    __syncwarp();
    // relu + cvt -> t (overwrites z region)
    #pragma unroll
    for (int n = 0; n < 8; n++) {
        float4 c = C[n];
        *(uint2*)(tb + r*68 + n*8 + 2*q)     = make_uint2(f2tf(fmaxf(c.x,0.f)), f2tf(fmaxf(c.y,0.f)));
        *(uint2*)(tb + (8+r)*68 + n*8 + 2*q) = make_uint2(f2tf(fmaxf(c.z,0.f)), f2tf(fmaxf(c.w,0.f)));
    }
    __syncwarp();

    // ---- GEMM2: t[16,64] @ W1b -> h1 (fp32) ----
    #pragma unroll
    for (int n = 0; n < 8; n++) {
        float2 bv = *(const float2*)(bib + n*8 + 2*q);
        C[n] = make_float4(bv.x, bv.y, bv.x, bv.y);
    }
    #pragma unroll
    for (int k = 0; k < 8; k++) {
        const uint4* wp = (const uint4*)(g_wf1b + k*512 + lane*16);
        uint4 f0 = __ldg(wp), f1 = __ldg(wp+1), f2 = __ldg(wp+2), f3 = __ldg(wp+3);
        u32 b0[8] = {f0.x,f0.y,f0.z,f0.w, f1.x,f1.y,f1.z,f1.w};
        u32 b1[8] = {f2.x,f2.y,f2.z,f2.w, f3.x,f3.y,f3.z,f3.w};
        u32 a0 = tb[r*68 + k*8 + q];
        u32 a1 = tb[(8+r)*68 + k*8 + q];
        u32 a2 = tb[r*68 + k*8 + q + 4];
        u32 a3 = tb[(8+r)*68 + k*8 + q + 4];
        #pragma unroll
        for (int n = 0; n < 8; n++) mma8(C[n], a0, a1, a2, a3, b0[n], b1[n]);
    }
    {
        float* o = g_h1 + (size_t)v*1024;
        #pragma unroll
        for (int n = 0; n < 8; n++) {
            float4 c = C[n];
            *(float2*)(o + r*64 + n*8 + 2*q)     = make_float2(fmaxf(c.x,0.f), fmaxf(c.y,0.f));
            *(float2*)(o + (8+r)*64 + n*8 + 2*q) = make_float2(fmaxf(c.z,0.f), fmaxf(c.w,0.f));
        }
    }
}

// ================= Kernel D: GIN layer 2 + sample-sum ======================
__global__ __launch_bounds__(256, 3) void kGin2(
    const float* __restrict__ eps2p,
    const float* __restrict__ b2a, const float* __restrict__ b2b,
    float* __restrict__ out)
{
    extern __shared__ u32 sh2[];
    float* bia = (float*)sh2;          // 64
    float* bib = bia + 64;             // 64
    u32*   zS  = (u32*)(bib + 64);     // 8 * 1088 (z then t)

    const int tid = threadIdx.x;
    if (tid < 64) { bia[tid] = b2a[tid]; bib[tid] = b2b[tid]; }
    __syncthreads();

    const int lane = tid & 31, w = tid >> 5;
    const int q = lane & 3, r = lane >> 2;
    const int v = blockIdx.x*8 + w;
    u32* zb = zS + w*1088;
    const float eps = 1.0f + eps2p[0];

    // ---- aggregation (fp32, 8 float4 in flight) -> z smem tf32 ----
    {
        float4 A[8];
        #pragma unroll
        for (int j = 0; j < 8; j++) A[j] = make_float4(0.f,0.f,0.f,0.f);
        const int cnt = min(g_cnt[v], CAP);
        const int* adj = g_adj + v*CAP;
        for (int e = 0; e < cnt; e++) {
            const float* src = g_h1 + (size_t)adj[e]*1024 + lane*4;
            #pragma unroll
            for (int j = 0; j < 8; j++) {
                float4 x = *(const float4*)(src + j*128);
                A[j].x+=x.x; A[j].y+=x.y; A[j].z+=x.z; A[j].w+=x.w;
            }
        }
        const float* own = g_h1 + (size_t)v*1024 + lane*4;
        #pragma unroll
        for (int j = 0; j < 8; j++) {
            float4 o = *(const float4*)(own + j*128);
            uint4 z;
            z.x = f2tf(fmaf(eps,o.x,A[j].x)); z.y = f2tf(fmaf(eps,o.y,A[j].y));
            z.z = f2tf(fmaf(eps,o.z,A[j].z)); z.w = f2tf(fmaf(eps,o.w,A[j].w));
            int m = 2*j + (lane >> 4), d0 = (lane & 15)*4;
            *(uint4*)(zb + m*68 + d0) = z;
        }
    }
    __syncwarp();

    float4 C[8];
    // ---- GEMM1: z @ W2a + b2a, relu ----
    #pragma unroll
    for (int n = 0; n < 8; n++) {
        float2 bv = *(const float2*)(bia + n*8 + 2*q);
        C[n] = make_float4(bv.x, bv.y, bv.x, bv.y);
    }
    #pragma unroll
    for (int k = 0; k < 8; k++) {
        const uint4* wp = (const uint4*)(g_wf2a + k*512 + lane*16);
        uint4 f0 = __ldg(wp), f1 = __ldg(wp+1), f2 = __ldg(wp+2), f3 = __ldg(wp+3);
        u32 b0[8] = {f0.x,f0.y,f0.z,f0.w, f1.x,f1.y,f1.z,f1.w};
        u32 b1[8] = {f2.x,f2.y,f2.z,f2.w, f3.x,f3.y,f3.z,f3.w};
        u32 a0 = zb[r*68 + k*8 + q];
        u32 a1 = zb[(8+r)*68 + k*8 + q];
        u32 a2 = zb[r*68 + k*8 + q + 4];
        u32 a3 = zb[(8+r)*68 + k*8 + q + 4];
        #pragma unroll
        for (int n = 0; n < 8; n++) mma8(C[n], a0, a1, a2, a3, b0[n], b1[n]);
    }
    __syncwarp();
    // relu + cvt -> t (overwrite z buffer)
    #pragma unroll
    for (int n = 0; n < 8; n++) {
        float4 c = C[n];
        *(uint2*)(zb + r*68 + n*8 + 2*q)     = make_uint2(f2tf(fmaxf(c.x,0.f)), f2tf(fmaxf(c.y,0.f)));
        *(uint2*)(zb + (8+r)*68 + n*8 + 2*q) = make_uint2(f2tf(fmaxf(c.z,0.f)), f2tf(fmaxf(c.w,0.f)));
    }
    __syncwarp();

    // ---- GEMM2: t @ W2b + b2b, relu, sum over m ----
    #pragma unroll
    for (int n = 0; n < 8; n++) {
        float2 bv = *(const float2*)(bib + n*8 + 2*q);
        C[n] = make_float4(bv.x, bv.y, bv.x, bv.y);
    }
    #pragma unroll
    for (int k = 0; k < 8; k++) {
        const uint4* wp = (const uint4*)(g_wf2b + k*512 + lane*16);
        uint4 f0 = __ldg(wp), f1 = __ldg(wp+1), f2 = __ldg(wp+2), f3 = __ldg(wp+3);
        u32 b0[8] = {f0.x,f0.y,f0.z,f0.w, f1.x,f1.y,f1.z,f1.w};
        u32 b1[8] = {f2.x,f2.y,f2.z,f2.w, f3.x,f3.y,f3.z,f3.w};
        u32 a0 = zb[r*68 + k*8 + q];
        u32 a1 = zb[(8+r)*68 + k*8 + q];
        u32 a2 = zb[r*68 + k*8 + q + 4];
        u32 a3 = zb[(8+r)*68 + k*8 + q + 4];
        #pragma unroll
        for (int n = 0; n < 8; n++) mma8(C[n], a0, a1, a2, a3, b0[n], b1[n]);
    }
    {
        float s0[8], s1[8];
        #pragma unroll
        for (int n = 0; n < 8; n++) {
            float4 c = C[n];
            s0[n] = fmaxf(c.x,0.f) + fmaxf(c.z,0.f);
            s1[n] = fmaxf(c.y,0.f) + fmaxf(c.w,0.f);
        }
        #pragma unroll
        for (int o = 4; o < 32; o <<= 1)
            #pragma unroll
            for (int n = 0; n < 8; n++) {
                s0[n] += __shfl_xor_sync(0xffffffffu, s0[n], o);
                s1[n] += __shfl_xor_sync(0xffffffffu, s1[n], o);
            }
        if (lane < 4) {
            float* op = out + (size_t)v*64;
            #pragma unroll
            for (int n = 0; n < 8; n++)
                *(float2*)(op + n*8 + 2*lane) = make_float2(s0[n], s1[n]);
        }
    }
}

// ================= launch ==================================================
extern "C" void kernel_launch(void* const* d_in, const int* in_sizes, int n_in,
                              void* d_out, int out_size)
{
    const float* lap  = (const float*)d_in[0];
    const float* W0   = (const float*)d_in[1];
    const float* mlpW = (const float*)d_in[2];
    const float* mlpb = (const float*)d_in[3];
    const float* bng  = (const float*)d_in[4];
    const float* bnb  = (const float*)d_in[5];
    const float* eps1 = (const float*)d_in[6];
    const float* W1a  = (const float*)d_in[7];
    const float* b1a  = (const float*)d_in[8];
    const float* W1b  = (const float*)d_in[9];
    const float* b1b  = (const float*)d_in[10];
    const float* eps2 = (const float*)d_in[11];
    const float* W2a  = (const float*)d_in[12];
    const float* b2a  = (const float*)d_in[13];
    const float* W2b  = (const float*)d_in[14];
    const float* b2b  = (const float*)d_in[15];
    const int*   ei   = (const int*)d_in[16];
    float* out = (float*)d_out;

    const int SMEM_A = 21696 * 4;                    // 86784 B
    const int SMEM_G = (128 + 8*1088) * 4;           // 35328 B -> 3 blocks/SM
    cudaFuncSetAttribute(kA,    cudaFuncAttributeMaxDynamicSharedMemorySize, SMEM_A);
    cudaFuncSetAttribute(kGin1, cudaFuncAttributeMaxDynamicSharedMemorySize, SMEM_G);
    cudaFuncSetAttribute(kGin2, cudaFuncAttributeMaxDynamicSharedMemorySize, SMEM_G);

    kFrag<<<16, 256>>>(W1a, W1b, W2a, W2b);
    kZero<<<NSUM/256, 256>>>();
    kFill<<<NE/256, 256>>>(ei);
    kA   <<<BG, 512, SMEM_A>>>(lap, W0, mlpW, mlpb, bng, bnb);
    kGin1<<<NSUM/8, 256, SMEM_G>>>(eps1, b1a, b1b);
    kGin2<<<NSUM/8, 256, SMEM_G>>>(eps2, b2a, b2b, out);
}